// round 13
// baseline (speedup 1.0000x reference)
#include <cuda_runtime.h>
#include <cuda_fp16.h>
#include <cstdint>

// ---------------- problem constants ----------------
#define N_RNA   2000
#define N_PROT  1512
#define NT      3512
#define SZ_R    3000
#define FUN_IN  5603
#define H_ATT   2048
#define H_FUN   4096
#define DCOLS   512
#define BATCH   8192
#define PROTEIN 1512
#define FLATSZ  8192
#define SPLITS2 8

#define M_PAD   3584            // 28 * 128
#define KP_ATT  3008            // 32-float multiple >= 3000
#define KP_FUN  5632            // 32-float multiple >= 5603

// scratch (half precision operand stores + f32 partials)
__device__ __half g_Ah[(size_t)M_PAD * KP_FUN];        // 40.4 MB
__device__ __half g_Bth[(size_t)H_FUN * KP_FUN];       // 46.1 MB
__device__ __half g_B2h[(size_t)256 * H_FUN];          // 2 MB
__device__ __half g_hidden_h[(size_t)NT * H_FUN];      // 28.8 MB
__device__ float  g_part[SPLITS2 * (size_t)NT * 256];  // 28.8 MB

// ---------------- helpers ----------------
__device__ __forceinline__ uint32_t smem_u32(const void* p) {
    uint32_t a;
    asm("{ .reg .u64 t; cvta.to.shared.u64 t, %1; cvt.u32.u64 %0, t; }" : "=r"(a) : "l"(p));
    return a;
}
__device__ __forceinline__ void mma_f16(float c[4],
                                        const uint32_t a[4], const uint32_t b[2]) {
    asm volatile(
        "mma.sync.aligned.m16n8k16.row.col.f32.f16.f16.f32 "
        "{%0,%1,%2,%3},{%4,%5,%6,%7},{%8,%9},{%0,%1,%2,%3};"
        : "+f"(c[0]), "+f"(c[1]), "+f"(c[2]), "+f"(c[3])
        : "r"(a[0]), "r"(a[1]), "r"(a[2]), "r"(a[3]), "r"(b[0]), "r"(b[1]));
}
#define CPA16(dst, src) \
    asm volatile("cp.async.ca.shared.global [%0], [%1], 16;" :: "r"(dst), "l"(src))
#define CP_COMMIT() asm volatile("cp.async.commit_group;" ::: "memory")

// packed f32x2 (Blackwell): FFMA2 path, PTX-only  (conv2, validated R8/R9)
#define PK2(d, lo, hi) \
    asm("mov.b64 %0, {%1, %2};" : "=l"(d) : "f"(lo), "f"(hi))
#define UPK2(lo, hi, s) \
    asm("mov.b64 {%0, %1}, %2;" : "=f"(lo), "=f"(hi) : "l"(s))
#define FMA2(d, a, b) \
    asm("fma.rn.f32x2 %0, %1, %2, %0;" : "+l"(d) : "l"(a), "l"(b))

// smem per stage: A [128 rows][80B] (10240) + B [128 n][80B] (10240)
#define KT        32            // K (halves==elements) per staged iter
#define A_BYTES   10240
#define STG_BYTES 20480
#define NSTAGE    4             // R11: 3 -> 4, prefetch distance now covers L2/DRAM latency

// =====================================================================
// fp16 mma.sync GEMM (m16n8k16), tile 128x128, KT=32, 4-stage cp.async.
//   A half [*, lda] K-major; Bt half [N][ldb] K-major (pre-transposed).
//   Both zero-padded in K to multiples of 32 -> unconditional 16B cp.async.
//   mode 0: CoutH[r][n] = half(gelu(acc + bias[n]))   (grid.z == 1)
//   mode 1: CoutF[z][r][n] = acc over K chunk z       (split-K, kLen | 32)
// Fragment word-indexing identical to the validated tf32 core (20-word rows).
// =====================================================================
__global__ __launch_bounds__(256, 2)
void gemm_f16(const __half* __restrict__ A, int lda, int Mreal,
              const __half* __restrict__ Bt, int ldb, int N, int kLen,
              const float* __restrict__ bias, __half* __restrict__ CoutH,
              float* __restrict__ CoutF, int mode)
{
    extern __shared__ __align__(16) char smemRaw[];
    uint32_t* smemW = (uint32_t*)smemRaw;
    const uint32_t smB = smem_u32(smemRaw);

    const int tid  = threadIdx.x;
    const int lane = tid & 31;
    const int wid  = tid >> 5;
    const int mWarp = (wid >> 2) * 64;
    const int nWarp = (wid & 3) * 32;
    const int rowTile = blockIdx.y * 128;
    const int colBase = blockIdx.x * 128;

    const int kBeg = blockIdx.z * kLen;
    const int nk   = kLen >> 5;                    // kLen multiple of 32 by construction

    // staging coords: thread -> one A row and one B row, two 16B chunks each
    const int sRow = tid >> 1;                     // 0..127
    const int cBase = (tid & 1) * 2;               // chunks {0,1} or {2,3}
    int gRow = rowTile + sRow; if (gRow >= Mreal) gRow = Mreal - 1;
    const __half* Arow = A + (size_t)gRow * lda;
    const __half* Brow = Bt + (size_t)(colBase + sRow) * ldb;
    const uint32_t sOff = (uint32_t)sRow * 80u + (uint32_t)cBase * 16u;

    float acc[4][4][4] = {};

    auto stage = [&](int buf, int k0) {
        uint32_t base = smB + (uint32_t)buf * STG_BYTES;
        CPA16(base + sOff,                 Arow + k0 + cBase * 8);
        CPA16(base + sOff + 16u,           Arow + k0 + cBase * 8 + 8);
        CPA16(base + A_BYTES + sOff,       Brow + k0 + cBase * 8);
        CPA16(base + A_BYTES + sOff + 16u, Brow + k0 + cBase * 8 + 8);
    };

    // prologue: fill NSTAGE-1 = 3 buffers
    stage(0, kBeg); CP_COMMIT();
    if (nk > 1) { stage(1, kBeg + KT);     CP_COMMIT(); }
    if (nk > 2) { stage(2, kBeg + 2 * KT); CP_COMMIT(); }

    for (int t = 0; t < nk; t++) {
        int rem = nk - 1 - t;                      // groups committed after buf t
        if (rem >= 2)      asm volatile("cp.async.wait_group 2;" ::: "memory");
        else if (rem == 1) asm volatile("cp.async.wait_group 1;" ::: "memory");
        else               asm volatile("cp.async.wait_group 0;" ::: "memory");
        __syncthreads();

        const uint32_t* As = smemW + (size_t)(t % NSTAGE) * (STG_BYTES / 4);
        const uint32_t* Bs = As + (A_BYTES / 4);

        #pragma unroll
        for (int ks = 0; ks < 2; ks++) {          // two k16 slabs per KT=32
            const int k8 = ks * 8;                 // word offset of slab
            uint32_t af[4][4], bf[4][2];
            #pragma unroll
            for (int mi = 0; mi < 4; mi++) {
                int m0 = mWarp + mi * 16 + (lane >> 2);
                const uint32_t* ap = &As[m0 * 20 + k8 + (lane & 3)];
                af[mi][0] = ap[0];
                af[mi][1] = ap[8 * 20];
                af[mi][2] = ap[4];
                af[mi][3] = ap[8 * 20 + 4];
            }
            #pragma unroll
            for (int ni = 0; ni < 4; ni++) {
                int n0 = nWarp + ni * 8 + (lane >> 2);
                const uint32_t* bp = &Bs[n0 * 20 + k8 + (lane & 3)];
                bf[ni][0] = bp[0];
                bf[ni][1] = bp[4];
            }
            #pragma unroll
            for (int mi = 0; mi < 4; mi++)
                #pragma unroll
                for (int ni = 0; ni < 4; ni++)
                    mma_f16(acc[mi][ni], af[mi], bf[ni]);
        }
        // buffer (t+3)%4 was last read at iter t-1, fenced by this iter's barrier.
        if (t + 3 < nk) {
            stage((t + 3) % NSTAGE, kBeg + (t + 3) * KT);
            CP_COMMIT();
        }
    }

    // ---- epilogue (C layout identical to validated core) ----
    #pragma unroll
    for (int mi = 0; mi < 4; mi++) {
        int r0 = rowTile + mWarp + mi * 16 + (lane >> 2);
        #pragma unroll
        for (int ni = 0; ni < 4; ni++) {
            int c = colBase + nWarp + ni * 8 + 2 * (lane & 3);
            float v0 = acc[mi][ni][0], v1 = acc[mi][ni][1];
            float v2 = acc[mi][ni][2], v3 = acc[mi][ni][3];
            if (mode == 0) {
                float2 bb = *(const float2*)(bias + c);
                v0 += bb.x; v1 += bb.y; v2 += bb.x; v3 += bb.y;
                v0 = 0.5f * v0 * (1.f + erff(v0 * 0.70710678118654752f));
                v1 = 0.5f * v1 * (1.f + erff(v1 * 0.70710678118654752f));
                v2 = 0.5f * v2 * (1.f + erff(v2 * 0.70710678118654752f));
                v3 = 0.5f * v3 * (1.f + erff(v3 * 0.70710678118654752f));
                if (r0 < Mreal)
                    *(__half2*)(CoutH + (size_t)r0 * N + c) = __floats2half2_rn(v0, v1);
                if (r0 + 8 < Mreal)
                    *(__half2*)(CoutH + (size_t)(r0 + 8) * N + c) = __floats2half2_rn(v2, v3);
            } else {
                float* outF = CoutF + (size_t)blockIdx.z * Mreal * N;
                if (r0 < Mreal)
                    *(float2*)(outF + (size_t)r0 * N + c) = make_float2(v0, v1);
                if (r0 + 8 < Mreal)
                    *(float2*)(outF + (size_t)(r0 + 8) * N + c) = make_float2(v2, v3);
            }
        }
    }
}

// ---------------- pack A: concat rows -> half [M_PAD][Kpad], zero-padded ------
__global__ __launch_bounds__(256)
void pack_A_h(const float* __restrict__ A0, const float* __restrict__ A1,
              int split, int Kreal, int Kpad, __half* __restrict__ dst)
{
    size_t i = (size_t)blockIdx.x * 256 + threadIdx.x;
    size_t tot = (size_t)M_PAD * (Kpad >> 2);
    if (i >= tot) return;
    int r = (int)(i / (Kpad >> 2));
    int k = (int)(i % (Kpad >> 2)) * 4;
    float v0 = 0.f, v1 = 0.f, v2 = 0.f, v3 = 0.f;
    if (r < NT) {
        const float* src = (r < split) ? (A0 + (size_t)r * Kreal)
                                       : (A1 + (size_t)(r - split) * Kreal);
        if (k     < Kreal) v0 = __ldg(src + k);
        if (k + 1 < Kreal) v1 = __ldg(src + k + 1);
        if (k + 2 < Kreal) v2 = __ldg(src + k + 2);
        if (k + 3 < Kreal) v3 = __ldg(src + k + 3);
    }
    __half2* d = (__half2*)(dst + (size_t)r * Kpad + k);
    d[0] = __floats2half2_rn(v0, v1);
    d[1] = __floats2half2_rn(v2, v3);
}

// ---------------- transpose+convert B [Kreal][N] f32 -> [N][Kpad] half --------
__global__ void convertB(const float* __restrict__ B, __half* __restrict__ Bt,
                         int Kreal, int Kpad, int N)
{
    __shared__ float tile[32][33];
    int n0 = blockIdx.x * 32, k0 = blockIdx.y * 32;
    int tx = threadIdx.x, ty = threadIdx.y;
    #pragma unroll
    for (int j = 0; j < 4; j++) {
        int k = k0 + ty + j * 8;
        tile[ty + j * 8][tx] = (k < Kreal) ? B[(size_t)k * N + n0 + tx] : 0.f;
    }
    __syncthreads();
    #pragma unroll
    for (int j = 0; j < 4; j++) {
        int n = n0 + ty + j * 8;
        Bt[(size_t)n * Kpad + k0 + tx] = __float2half_rn(tile[tx][ty + j * 8]);
    }
}

// ---------------- split-K reduce + sigmoid (unchanged) ----------------
__global__ __launch_bounds__(256)
void gemm2_reduce(const float* __restrict__ part, const float* __restrict__ bias,
                  float* __restrict__ E, int M, int colOff)
{
    int idx = blockIdx.x * 256 + threadIdx.x;
    if (idx >= M * 256) return;
    int r = idx >> 8, c = idx & 255;
    float s = 0.f;
    #pragma unroll
    for (int z = 0; z < SPLITS2; z++)
        s += part[((size_t)z * M + r) * 256 + c];
    s += bias[c];
    s = 1.f / (1.f + __expf(-s));
    E[(size_t)r * DCOLS + colOff + c] = s;
}

// ---------------- fused conv stack (unchanged, validated R9) ----------------
__global__ __launch_bounds__(256)
void conv_fused(const float* __restrict__ e, const int* __restrict__ idx,
                const float* __restrict__ w1, const float* __restrict__ b1,
                const float* __restrict__ w2, const float* __restrict__ b2,
                const float* __restrict__ Wout, const float* __restrict__ bout,
                float* __restrict__ outP, float* __restrict__ flatP)
{
    extern __shared__ float sm[];
    float* xs  = sm;             // 1032
    float* p1s = xs + 1032;      // 8320
    float* w1s = p1s + 8320;     // 240
    float* b1s = w1s + 240;      // 16
    float* b2s = b1s + 16;       // 32
    float* wdup = b2s + 32;      // 7680
    __shared__ float redsum[8][2];

    int t = threadIdx.x;
    int b = blockIdx.x;

    for (int i = t; i < 240; i += 256)  w1s[i] = w1[i];
    if (t < 16) b1s[t] = b1[t];
    if (t < 32) b2s[t] = b2[t];

    int id  = idx[b];
    int rno = id / PROTEIN;
    int pno = id - rno * PROTEIN;
    const float* row0 = e + (size_t)rno * DCOLS;
    const float* row1 = e + (size_t)(N_RNA + pno) * DCOLS;
    for (int i = t; i < 1032; i += 256) {
        int rr = (i >= 516), c = i - rr * 516;
        float v = 0.f;
        if (c >= 2 && c < 514) v = (rr == 0 ? row0 : row1)[c - 2];
        xs[i] = v;
    }
    if (t < 128) {
        int rr = t >> 2, j = t & 3;
        int col = (j < 2) ? j : 256 + j;
        p1s[rr * 260 + col] = 0.f;
    }
    __syncthreads();

    for (int li = t; li < 8192; li += 256) {
        int c = li >> 9, ph = (li >> 8) & 1, pw = li & 255;
        const float* wc = &w1s[c * 15];
        float bb = b1s[c];
        float s = 0.f;
        #pragma unroll
        for (int d = 0; d < 4; d++) {
            int h = 2 * ph + (d >> 1);
            int w = 2 * pw + (d & 1);
            float acc = bb;
            #pragma unroll
            for (int kh = 0; kh < 3; kh++) {
                int r = h + kh - 2;
                if (r >= 0 && r < 2) {
                    #pragma unroll
                    for (int kw = 0; kw < 5; kw++)
                        acc += wc[kh * 5 + kw] * xs[r * 516 + w + kw];
                }
            }
            s += (acc >= 0.f) ? acc : 0.01f * acc;
        }
        p1s[(c * 2 + ph) * 260 + pw + 2] = 0.25f * s;
    }

    int ph = t >> 7;
    int pw = t & 127;
    float o0 = 0.f, o1 = 0.f;

    for (int pass = 0; pass < 2; pass++) {
        __syncthreads();
        for (int i = t; i < 3840; i += 256) {
            float w = w2[pass * 3840 + i];
            ((float2*)wdup)[i] = make_float2(w, w);
        }
        __syncthreads();

        for (int cb = 0; cb < 16; cb += 8) {
            unsigned long long acc01[8], acc23[8];
            #pragma unroll
            for (int j = 0; j < 8; j++) {
                float bb = b2s[pass * 16 + cb + j];
                PK2(acc01[j], bb, bb);
                acc23[j] = acc01[j];
            }
            for (int ci = 0; ci < 16; ci++) {
                const float2* q0 = (const float2*)&p1s[(ci * 2 + 0) * 260 + 2 * pw];
                const float2* q1 = (const float2*)&p1s[(ci * 2 + 1) * 260 + 2 * pw];
                float2 u0 = q0[0], u1 = q0[1], u2 = q0[2];
                float2 v0 = q1[0], v1 = q1[1], v2 = q1[2];
                unsigned long long p0[5], p1p[5];
                PK2(p0[0],  u0.x, u0.y); PK2(p0[1],  u0.y, u1.x); PK2(p0[2],  u1.x, u1.y);
                PK2(p0[3],  u1.y, u2.x); PK2(p0[4],  u2.x, u2.y);
                PK2(p1p[0], v0.x, v0.y); PK2(p1p[1], v0.y, v1.x); PK2(p1p[2], v1.x, v1.y);
                PK2(p1p[3], v1.y, v2.x); PK2(p1p[4], v2.x, v2.y);
                #pragma unroll
                for (int j = 0; j < 8; j++) {
                    const unsigned long long* wd =
                        (const unsigned long long*)&wdup[((cb + j) * 240 + ci * 15) * 2];
                    if (ph == 0) {
                        #pragma unroll
                        for (int kw = 0; kw < 5; kw++) {
                            unsigned long long wA = wd[10 + kw], wB = wd[5 + kw];
                            FMA2(acc01[j], wA, p0[kw]);
                            FMA2(acc23[j], wB, p0[kw]);
                            FMA2(acc23[j], wA, p1p[kw]);
                        }
                    } else {
                        #pragma unroll
                        for (int kw = 0; kw < 5; kw++) {
                            unsigned long long wA = wd[kw], wB = wd[5 + kw];
                            FMA2(acc01[j], wA, p0[kw]);
                            FMA2(acc01[j], wB, p1p[kw]);
                            FMA2(acc23[j], wA, p1p[kw]);
                        }
                    }
                }
            }
            #pragma unroll
            for (int j = 0; j < 8; j++) {
                float a0, a1, a2, a3;
                UPK2(a0, a1, acc01[j]);
                UPK2(a2, a3, acc23[j]);
                a0 = (a0 >= 0.f) ? a0 : 0.01f * a0;
                a1 = (a1 >= 0.f) ? a1 : 0.01f * a1;
                a2 = (a2 >= 0.f) ? a2 : 0.01f * a2;
                a3 = (a3 >= 0.f) ? a3 : 0.01f * a3;
                float m  = fmaxf(fmaxf(a0, a1), fmaxf(a2, a3));
                float tv = tanhf(m);
                int fi = (pass * 16 + cb + j) * 256 + ph * 128 + pw;
                flatP[(size_t)b * FLATSZ + fi] = tv;
                o0 += tv * Wout[2 * fi];
                o1 += tv * Wout[2 * fi + 1];
            }
        }
    }

    #pragma unroll
    for (int off = 16; off > 0; off >>= 1) {
        o0 += __shfl_down_sync(0xffffffffu, o0, off);
        o1 += __shfl_down_sync(0xffffffffu, o1, off);
    }
    if ((t & 31) == 0) { redsum[t >> 5][0] = o0; redsum[t >> 5][1] = o1; }
    __syncthreads();
    if (t == 0) {
        float s0 = 0.f, s1 = 0.f;
        #pragma unroll
        for (int w = 0; w < 8; w++) { s0 += redsum[w][0]; s1 += redsum[w][1]; }
        outP[2 * b]     = s0 + bout[0];
        outP[2 * b + 1] = s1 + bout[1];
    }
}

// ---------------- launch ----------------
extern "C" void kernel_launch(void* const* d_in, const int* in_sizes, int n_in,
                              void* d_out, int out_size)
{
    (void)in_sizes; (void)n_in; (void)out_size;
    const float* r_att   = (const float*)d_in[0];
    const float* p_att   = (const float*)d_in[1];
    const float* r_fun   = (const float*)d_in[2];
    const float* p_fun   = (const float*)d_in[3];
    const int*   idx     = (const int*)  d_in[4];
    const float* W_att1  = (const float*)d_in[5];
    const float* b_att1  = (const float*)d_in[6];
    const float* W_att2  = (const float*)d_in[7];
    const float* b_att2  = (const float*)d_in[8];
    const float* W_fun1  = (const float*)d_in[9];
    const float* b_fun1  = (const float*)d_in[10];
    const float* W_fun2  = (const float*)d_in[11];
    const float* b_fun2  = (const float*)d_in[12];
    const float* conv1_w = (const float*)d_in[13];
    const float* conv1_b = (const float*)d_in[14];
    const float* conv2_w = (const float*)d_in[15];
    const float* conv2_b = (const float*)d_in[16];
    const float* W_out   = (const float*)d_in[17];
    const float* b_out   = (const float*)d_in[18];

    float* out   = (float*)d_out;
    float* e     = out;                              // [3512, 512]
    float* outP  = out + (size_t)NT * DCOLS;         // [8192, 2]
    float* flatP = outP + 2 * BATCH;                 // [8192, 8192]

    __half *Ah, *Bth, *B2h, *hiddenH;
    float  *part;
    cudaGetSymbolAddress((void**)&Ah,      g_Ah);
    cudaGetSymbolAddress((void**)&Bth,     g_Bth);
    cudaGetSymbolAddress((void**)&B2h,     g_B2h);
    cudaGetSymbolAddress((void**)&hiddenH, g_hidden_h);
    cudaGetSymbolAddress((void**)&part,    g_part);

    const int gemmSmem = NSTAGE * STG_BYTES + 16;    // 81936
    cudaFuncSetAttribute(gemm_f16, cudaFuncAttributeMaxDynamicSharedMemorySize, gemmSmem);

    const int mT = (NT + 127) / 128;                 // 28

    // ===== ATT branch =====
    {
        size_t n4 = (size_t)M_PAD * (KP_ATT / 4);
        pack_A_h<<<(unsigned)((n4 + 255) / 256), 256>>>(r_att, p_att, N_RNA, SZ_R, KP_ATT, Ah);
        convertB<<<dim3(H_ATT / 32, KP_ATT / 32), dim3(32, 8)>>>(W_att1, Bth, SZ_R, KP_ATT, H_ATT);
        gemm_f16<<<dim3(H_ATT / 128, mT, 1), 256, gemmSmem>>>(
            Ah, KP_ATT, NT, Bth, KP_ATT, H_ATT, KP_ATT, b_att1, hiddenH, nullptr, 0);
        convertB<<<dim3(256 / 32, H_ATT / 32), dim3(32, 8)>>>(W_att2, B2h, H_ATT, H_ATT, 256);
        gemm_f16<<<dim3(2, mT, SPLITS2), 256, gemmSmem>>>(
            hiddenH, H_ATT, NT, B2h, H_ATT, 256, H_ATT / SPLITS2, nullptr, nullptr, part, 1);
        gemm2_reduce<<<(NT * 256 + 255) / 256, 256>>>(part, b_att2, e, NT, 0);
    }
    // ===== FUN branch =====
    {
        size_t n4 = (size_t)M_PAD * (KP_FUN / 4);
        pack_A_h<<<(unsigned)((n4 + 255) / 256), 256>>>(r_fun, p_fun, N_RNA, FUN_IN, KP_FUN, Ah);
        convertB<<<dim3(H_FUN / 32, KP_FUN / 32), dim3(32, 8)>>>(W_fun1, Bth, FUN_IN, KP_FUN, H_FUN);
        gemm_f16<<<dim3(H_FUN / 128, mT, 1), 256, gemmSmem>>>(
            Ah, KP_FUN, NT, Bth, KP_FUN, H_FUN, KP_FUN, b_fun1, hiddenH, nullptr, 0);
        convertB<<<dim3(256 / 32, H_FUN / 32), dim3(32, 8)>>>(W_fun2, B2h, H_FUN, H_FUN, 256);
        gemm_f16<<<dim3(2, mT, SPLITS2), 256, gemmSmem>>>(
            hiddenH, H_FUN, NT, B2h, H_FUN, 256, H_FUN / SPLITS2, nullptr, nullptr, part, 1);
        gemm2_reduce<<<(NT * 256 + 255) / 256, 256>>>(part, b_fun2, e, NT, 256);
    }

    // fused conv stack — unchanged (69280 B smem, 3 CTAs/SM)
    const int convSmem = 17320 * 4;
    cudaFuncSetAttribute(conv_fused, cudaFuncAttributeMaxDynamicSharedMemorySize, convSmem);
    conv_fused<<<BATCH, 256, convSmem>>>(e, idx, conv1_w, conv1_b, conv2_w, conv2_b,
                                         W_out, b_out, outP, flatP);
}

// round 15
// speedup vs baseline: 1.0688x; 1.0688x over previous
#include <cuda_runtime.h>
#include <cuda_fp16.h>
#include <cstdint>

// ---------------- problem constants ----------------
#define N_RNA   2000
#define N_PROT  1512
#define NT      3512
#define SZ_R    3000
#define FUN_IN  5603
#define H_ATT   2048
#define H_FUN   4096
#define DCOLS   512
#define BATCH   8192
#define PROTEIN 1512
#define FLATSZ  8192
#define SPLITS2 8

#define M_PAD   3584            // 28 * 128
#define KP_ATT  3008            // 32-float multiple >= 3000
#define KP_FUN  5632            // 32-float multiple >= 5603

// scratch (half precision operand stores + f32 partials)
__device__ __half g_Ah[(size_t)M_PAD * KP_FUN];        // 40.4 MB
__device__ __half g_Bth[(size_t)H_FUN * KP_FUN];       // 46.1 MB
__device__ __half g_B2h[(size_t)256 * H_FUN];          // 2 MB
__device__ __half g_hidden_h[(size_t)NT * H_FUN];      // 28.8 MB
__device__ float  g_part[SPLITS2 * (size_t)NT * 256];  // 28.8 MB

// ---------------- helpers ----------------
__device__ __forceinline__ uint32_t smem_u32(const void* p) {
    uint32_t a;
    asm("{ .reg .u64 t; cvta.to.shared.u64 t, %1; cvt.u32.u64 %0, t; }" : "=r"(a) : "l"(p));
    return a;
}
__device__ __forceinline__ void mma_f16(float c[4],
                                        const uint32_t a[4], const uint32_t b[2]) {
    asm volatile(
        "mma.sync.aligned.m16n8k16.row.col.f32.f16.f16.f32 "
        "{%0,%1,%2,%3},{%4,%5,%6,%7},{%8,%9},{%0,%1,%2,%3};"
        : "+f"(c[0]), "+f"(c[1]), "+f"(c[2]), "+f"(c[3])
        : "r"(a[0]), "r"(a[1]), "r"(a[2]), "r"(a[3]), "r"(b[0]), "r"(b[1]));
}
#define LDSM_X4(r0, r1, r2, r3, addr) \
    asm volatile("ldmatrix.sync.aligned.m8n8.x4.shared.b16 {%0,%1,%2,%3}, [%4];" \
        : "=r"(r0), "=r"(r1), "=r"(r2), "=r"(r3) : "r"(addr))
#define CPA16(dst, src) \
    asm volatile("cp.async.ca.shared.global [%0], [%1], 16;" :: "r"(dst), "l"(src))
#define CP_COMMIT() asm volatile("cp.async.commit_group;" ::: "memory")

// packed f32x2 (Blackwell): FFMA2 path, PTX-only  (conv2, validated R8/R9)
#define PK2(d, lo, hi) \
    asm("mov.b64 %0, {%1, %2};" : "=l"(d) : "f"(lo), "f"(hi))
#define UPK2(lo, hi, s) \
    asm("mov.b64 {%0, %1}, %2;" : "=f"(lo), "=f"(hi) : "l"(s))
#define FMA2(d, a, b) \
    asm("fma.rn.f32x2 %0, %1, %2, %0;" : "+l"(d) : "l"(a), "l"(b))

// smem per stage: A [128 rows][80B] (10240) + B [128 n][80B] (10240)
#define KT        32            // K (halves==elements) per staged iter
#define A_BYTES   10240
#define STG_BYTES 20480
#define NSTAGE    3             // back to best-measured R10 config

// =====================================================================
// fp16 mma.sync GEMM (m16n8k16), tile 128x128, KT=32, 3-stage cp.async.
// R14: fragment loads via ldmatrix.x4 (48 LDS.32 -> 12 LDSM per iter);
// lane mapping derived from and identical to the validated scalar loads.
//   mode 0: CoutH[r][n] = half(gelu(acc + bias[n]))   (grid.z == 1)
//   mode 1: CoutF[z][r][n] = acc over K chunk z       (split-K, kLen | 32)
// =====================================================================
__global__ __launch_bounds__(256, 2)
void gemm_f16(const __half* __restrict__ A, int lda, int Mreal,
              const __half* __restrict__ Bt, int ldb, int N, int kLen,
              const float* __restrict__ bias, __half* __restrict__ CoutH,
              float* __restrict__ CoutF, int mode)
{
    extern __shared__ __align__(16) char smemRaw[];
    const uint32_t smB = smem_u32(smemRaw);

    const int tid  = threadIdx.x;
    const int lane = tid & 31;
    const int wid  = tid >> 5;
    const int mWarp = (wid >> 2) * 64;
    const int nWarp = (wid & 3) * 32;
    const int rowTile = blockIdx.y * 128;
    const int colBase = blockIdx.x * 128;

    const int kBeg = blockIdx.z * kLen;
    const int nk   = kLen >> 5;                    // kLen multiple of 32

    // staging coords: thread -> one A row and one B row, two 16B chunks each
    const int sRow = tid >> 1;                     // 0..127
    const int cBase = (tid & 1) * 2;               // chunks {0,1} or {2,3}
    int gRow = rowTile + sRow; if (gRow >= Mreal) gRow = Mreal - 1;
    const __half* Arow = A + (size_t)gRow * lda;
    const __half* Brow = Bt + (size_t)(colBase + sRow) * ldb;
    const uint32_t sOff = (uint32_t)sRow * 80u + (uint32_t)cBase * 16u;

    // ldmatrix per-lane address offsets (within a stage buffer, before ks term)
    //   A tiles: T0=(m0-7,w0-3) T1=(m8-15,w0-3) T2=(m0-7,w4-7) T3=(m8-15,w4-7)
    const uint32_t aLdRow = (uint32_t)(mWarp + (lane & 7) + ((lane >> 3) & 1) * 8);
    const uint32_t aLdOff = aLdRow * 80u + ((uint32_t)(lane >> 4)) * 16u;
    //   B tiles: T0=(n0-7,w0-3) T1=(n0-7,w4-7) T2=(n8-15,w0-3) T3=(n8-15,w4-7)
    const uint32_t bLdRow = (uint32_t)(nWarp + (lane & 7) + ((lane >> 4) & 1) * 8);
    const uint32_t bLdOff = bLdRow * 80u + ((uint32_t)((lane >> 3) & 1)) * 16u;

    float acc[4][4][4] = {};

    auto stage = [&](int buf, int k0) {
        uint32_t base = smB + (uint32_t)buf * STG_BYTES;
        CPA16(base + sOff,                 Arow + k0 + cBase * 8);
        CPA16(base + sOff + 16u,           Arow + k0 + cBase * 8 + 8);
        CPA16(base + A_BYTES + sOff,       Brow + k0 + cBase * 8);
        CPA16(base + A_BYTES + sOff + 16u, Brow + k0 + cBase * 8 + 8);
    };

    stage(0, kBeg); CP_COMMIT();
    if (nk > 1) { stage(1, kBeg + KT); CP_COMMIT(); }

    for (int t = 0; t < nk; t++) {
        if (t + 1 < nk) asm volatile("cp.async.wait_group 1;" ::: "memory");
        else            asm volatile("cp.async.wait_group 0;" ::: "memory");
        __syncthreads();

        const uint32_t sA = smB + (uint32_t)(t % NSTAGE) * STG_BYTES;
        const uint32_t sBf = sA + A_BYTES;

        #pragma unroll
        for (int ks = 0; ks < 2; ks++) {          // two k16 slabs per KT=32
            const uint32_t kByte = (uint32_t)ks * 32u;
            uint32_t af[4][4], bf[4][2];
            #pragma unroll
            for (int mi = 0; mi < 4; mi++) {
                uint32_t addr = sA + aLdOff + (uint32_t)mi * (16u * 80u) + kByte;
                LDSM_X4(af[mi][0], af[mi][1], af[mi][2], af[mi][3], addr);
            }
            #pragma unroll
            for (int pair = 0; pair < 2; pair++) {  // covers ni = 2*pair, 2*pair+1
                uint32_t addr = sBf + bLdOff + (uint32_t)pair * (16u * 80u) + kByte;
                LDSM_X4(bf[2 * pair][0], bf[2 * pair][1],
                        bf[2 * pair + 1][0], bf[2 * pair + 1][1], addr);
            }
            #pragma unroll
            for (int mi = 0; mi < 4; mi++)
                #pragma unroll
                for (int ni = 0; ni < 4; ni++)
                    mma_f16(acc[mi][ni], af[mi], bf[ni]);
        }
        if (t + 2 < nk) {
            stage((t + 2) % NSTAGE, kBeg + (t + 2) * KT);
            CP_COMMIT();
        }
    }

    // ---- epilogue (identical to validated core) ----
    #pragma unroll
    for (int mi = 0; mi < 4; mi++) {
        int r0 = rowTile + mWarp + mi * 16 + (lane >> 2);
        #pragma unroll
        for (int ni = 0; ni < 4; ni++) {
            int c = colBase + nWarp + ni * 8 + 2 * (lane & 3);
            float v0 = acc[mi][ni][0], v1 = acc[mi][ni][1];
            float v2 = acc[mi][ni][2], v3 = acc[mi][ni][3];
            if (mode == 0) {
                float2 bb = *(const float2*)(bias + c);
                v0 += bb.x; v1 += bb.y; v2 += bb.x; v3 += bb.y;
                v0 = 0.5f * v0 * (1.f + erff(v0 * 0.70710678118654752f));
                v1 = 0.5f * v1 * (1.f + erff(v1 * 0.70710678118654752f));
                v2 = 0.5f * v2 * (1.f + erff(v2 * 0.70710678118654752f));
                v3 = 0.5f * v3 * (1.f + erff(v3 * 0.70710678118654752f));
                if (r0 < Mreal)
                    *(__half2*)(CoutH + (size_t)r0 * N + c) = __floats2half2_rn(v0, v1);
                if (r0 + 8 < Mreal)
                    *(__half2*)(CoutH + (size_t)(r0 + 8) * N + c) = __floats2half2_rn(v2, v3);
            } else {
                float* outF = CoutF + (size_t)blockIdx.z * Mreal * N;
                if (r0 < Mreal)
                    *(float2*)(outF + (size_t)r0 * N + c) = make_float2(v0, v1);
                if (r0 + 8 < Mreal)
                    *(float2*)(outF + (size_t)(r0 + 8) * N + c) = make_float2(v2, v3);
            }
        }
    }
}

// ---------------- pack A: concat rows -> half [M_PAD][Kpad], zero-padded ------
__global__ __launch_bounds__(256)
void pack_A_h(const float* __restrict__ A0, const float* __restrict__ A1,
              int split, int Kreal, int Kpad, __half* __restrict__ dst)
{
    size_t i = (size_t)blockIdx.x * 256 + threadIdx.x;
    size_t tot = (size_t)M_PAD * (Kpad >> 2);
    if (i >= tot) return;
    int r = (int)(i / (Kpad >> 2));
    int k = (int)(i % (Kpad >> 2)) * 4;
    float v0 = 0.f, v1 = 0.f, v2 = 0.f, v3 = 0.f;
    if (r < NT) {
        const float* src = (r < split) ? (A0 + (size_t)r * Kreal)
                                       : (A1 + (size_t)(r - split) * Kreal);
        if (k     < Kreal) v0 = __ldg(src + k);
        if (k + 1 < Kreal) v1 = __ldg(src + k + 1);
        if (k + 2 < Kreal) v2 = __ldg(src + k + 2);
        if (k + 3 < Kreal) v3 = __ldg(src + k + 3);
    }
    __half2* d = (__half2*)(dst + (size_t)r * Kpad + k);
    d[0] = __floats2half2_rn(v0, v1);
    d[1] = __floats2half2_rn(v2, v3);
}

// ---------------- transpose+convert B [Kreal][N] f32 -> [N][Kpad] half --------
__global__ void convertB(const float* __restrict__ B, __half* __restrict__ Bt,
                         int Kreal, int Kpad, int N)
{
    __shared__ float tile[32][33];
    int n0 = blockIdx.x * 32, k0 = blockIdx.y * 32;
    int tx = threadIdx.x, ty = threadIdx.y;
    #pragma unroll
    for (int j = 0; j < 4; j++) {
        int k = k0 + ty + j * 8;
        tile[ty + j * 8][tx] = (k < Kreal) ? B[(size_t)k * N + n0 + tx] : 0.f;
    }
    __syncthreads();
    #pragma unroll
    for (int j = 0; j < 4; j++) {
        int n = n0 + ty + j * 8;
        Bt[(size_t)n * Kpad + k0 + tx] = __float2half_rn(tile[tx][ty + j * 8]);
    }
}

// ---------------- split-K reduce + sigmoid (unchanged) ----------------
__global__ __launch_bounds__(256)
void gemm2_reduce(const float* __restrict__ part, const float* __restrict__ bias,
                  float* __restrict__ E, int M, int colOff)
{
    int idx = blockIdx.x * 256 + threadIdx.x;
    if (idx >= M * 256) return;
    int r = idx >> 8, c = idx & 255;
    float s = 0.f;
    #pragma unroll
    for (int z = 0; z < SPLITS2; z++)
        s += part[((size_t)z * M + r) * 256 + c];
    s += bias[c];
    s = 1.f / (1.f + __expf(-s));
    E[(size_t)r * DCOLS + colOff + c] = s;
}

// ---------------- fused conv stack (unchanged, validated R9) ----------------
__global__ __launch_bounds__(256)
void conv_fused(const float* __restrict__ e, const int* __restrict__ idx,
                const float* __restrict__ w1, const float* __restrict__ b1,
                const float* __restrict__ w2, const float* __restrict__ b2,
                const float* __restrict__ Wout, const float* __restrict__ bout,
                float* __restrict__ outP, float* __restrict__ flatP)
{
    extern __shared__ float sm[];
    float* xs  = sm;             // 1032
    float* p1s = xs + 1032;      // 8320
    float* w1s = p1s + 8320;     // 240
    float* b1s = w1s + 240;      // 16
    float* b2s = b1s + 16;       // 32
    float* wdup = b2s + 32;      // 7680
    __shared__ float redsum[8][2];

    int t = threadIdx.x;
    int b = blockIdx.x;

    for (int i = t; i < 240; i += 256)  w1s[i] = w1[i];
    if (t < 16) b1s[t] = b1[t];
    if (t < 32) b2s[t] = b2[t];

    int id  = idx[b];
    int rno = id / PROTEIN;
    int pno = id - rno * PROTEIN;
    const float* row0 = e + (size_t)rno * DCOLS;
    const float* row1 = e + (size_t)(N_RNA + pno) * DCOLS;
    for (int i = t; i < 1032; i += 256) {
        int rr = (i >= 516), c = i - rr * 516;
        float v = 0.f;
        if (c >= 2 && c < 514) v = (rr == 0 ? row0 : row1)[c - 2];
        xs[i] = v;
    }
    if (t < 128) {
        int rr = t >> 2, j = t & 3;
        int col = (j < 2) ? j : 256 + j;
        p1s[rr * 260 + col] = 0.f;
    }
    __syncthreads();

    for (int li = t; li < 8192; li += 256) {
        int c = li >> 9, ph = (li >> 8) & 1, pw = li & 255;
        const float* wc = &w1s[c * 15];
        float bb = b1s[c];
        float s = 0.f;
        #pragma unroll
        for (int d = 0; d < 4; d++) {
            int h = 2 * ph + (d >> 1);
            int w = 2 * pw + (d & 1);
            float acc = bb;
            #pragma unroll
            for (int kh = 0; kh < 3; kh++) {
                int r = h + kh - 2;
                if (r >= 0 && r < 2) {
                    #pragma unroll
                    for (int kw = 0; kw < 5; kw++)
                        acc += wc[kh * 5 + kw] * xs[r * 516 + w + kw];
                }
            }
            s += (acc >= 0.f) ? acc : 0.01f * acc;
        }
        p1s[(c * 2 + ph) * 260 + pw + 2] = 0.25f * s;
    }

    int ph = t >> 7;
    int pw = t & 127;
    float o0 = 0.f, o1 = 0.f;

    for (int pass = 0; pass < 2; pass++) {
        __syncthreads();
        for (int i = t; i < 3840; i += 256) {
            float w = w2[pass * 3840 + i];
            ((float2*)wdup)[i] = make_float2(w, w);
        }
        __syncthreads();

        for (int cb = 0; cb < 16; cb += 8) {
            unsigned long long acc01[8], acc23[8];
            #pragma unroll
            for (int j = 0; j < 8; j++) {
                float bb = b2s[pass * 16 + cb + j];
                PK2(acc01[j], bb, bb);
                acc23[j] = acc01[j];
            }
            for (int ci = 0; ci < 16; ci++) {
                const float2* q0 = (const float2*)&p1s[(ci * 2 + 0) * 260 + 2 * pw];
                const float2* q1 = (const float2*)&p1s[(ci * 2 + 1) * 260 + 2 * pw];
                float2 u0 = q0[0], u1 = q0[1], u2 = q0[2];
                float2 v0 = q1[0], v1 = q1[1], v2 = q1[2];
                unsigned long long p0[5], p1p[5];
                PK2(p0[0],  u0.x, u0.y); PK2(p0[1],  u0.y, u1.x); PK2(p0[2],  u1.x, u1.y);
                PK2(p0[3],  u1.y, u2.x); PK2(p0[4],  u2.x, u2.y);
                PK2(p1p[0], v0.x, v0.y); PK2(p1p[1], v0.y, v1.x); PK2(p1p[2], v1.x, v1.y);
                PK2(p1p[3], v1.y, v2.x); PK2(p1p[4], v2.x, v2.y);
                #pragma unroll
                for (int j = 0; j < 8; j++) {
                    const unsigned long long* wd =
                        (const unsigned long long*)&wdup[((cb + j) * 240 + ci * 15) * 2];
                    if (ph == 0) {
                        #pragma unroll
                        for (int kw = 0; kw < 5; kw++) {
                            unsigned long long wA = wd[10 + kw], wB = wd[5 + kw];
                            FMA2(acc01[j], wA, p0[kw]);
                            FMA2(acc23[j], wB, p0[kw]);
                            FMA2(acc23[j], wA, p1p[kw]);
                        }
                    } else {
                        #pragma unroll
                        for (int kw = 0; kw < 5; kw++) {
                            unsigned long long wA = wd[kw], wB = wd[5 + kw];
                            FMA2(acc01[j], wA, p0[kw]);
                            FMA2(acc01[j], wB, p1p[kw]);
                            FMA2(acc23[j], wA, p1p[kw]);
                        }
                    }
                }
            }
            #pragma unroll
            for (int j = 0; j < 8; j++) {
                float a0, a1, a2, a3;
                UPK2(a0, a1, acc01[j]);
                UPK2(a2, a3, acc23[j]);
                a0 = (a0 >= 0.f) ? a0 : 0.01f * a0;
                a1 = (a1 >= 0.f) ? a1 : 0.01f * a1;
                a2 = (a2 >= 0.f) ? a2 : 0.01f * a2;
                a3 = (a3 >= 0.f) ? a3 : 0.01f * a3;
                float m  = fmaxf(fmaxf(a0, a1), fmaxf(a2, a3));
                float tv = tanhf(m);
                int fi = (pass * 16 + cb + j) * 256 + ph * 128 + pw;
                flatP[(size_t)b * FLATSZ + fi] = tv;
                o0 += tv * Wout[2 * fi];
                o1 += tv * Wout[2 * fi + 1];
            }
        }
    }

    #pragma unroll
    for (int off = 16; off > 0; off >>= 1) {
        o0 += __shfl_down_sync(0xffffffffu, o0, off);
        o1 += __shfl_down_sync(0xffffffffu, o1, off);
    }
    if ((t & 31) == 0) { redsum[t >> 5][0] = o0; redsum[t >> 5][1] = o1; }
    __syncthreads();
    if (t == 0) {
        float s0 = 0.f, s1 = 0.f;
        #pragma unroll
        for (int w = 0; w < 8; w++) { s0 += redsum[w][0]; s1 += redsum[w][1]; }
        outP[2 * b]     = s0 + bout[0];
        outP[2 * b + 1] = s1 + bout[1];
    }
}

// ---------------- launch ----------------
extern "C" void kernel_launch(void* const* d_in, const int* in_sizes, int n_in,
                              void* d_out, int out_size)
{
    (void)in_sizes; (void)n_in; (void)out_size;
    const float* r_att   = (const float*)d_in[0];
    const float* p_att   = (const float*)d_in[1];
    const float* r_fun   = (const float*)d_in[2];
    const float* p_fun   = (const float*)d_in[3];
    const int*   idx     = (const int*)  d_in[4];
    const float* W_att1  = (const float*)d_in[5];
    const float* b_att1  = (const float*)d_in[6];
    const float* W_att2  = (const float*)d_in[7];
    const float* b_att2  = (const float*)d_in[8];
    const float* W_fun1  = (const float*)d_in[9];
    const float* b_fun1  = (const float*)d_in[10];
    const float* W_fun2  = (const float*)d_in[11];
    const float* b_fun2  = (const float*)d_in[12];
    const float* conv1_w = (const float*)d_in[13];
    const float* conv1_b = (const float*)d_in[14];
    const float* conv2_w = (const float*)d_in[15];
    const float* conv2_b = (const float*)d_in[16];
    const float* W_out   = (const float*)d_in[17];
    const float* b_out   = (const float*)d_in[18];

    float* out   = (float*)d_out;
    float* e     = out;                              // [3512, 512]
    float* outP  = out + (size_t)NT * DCOLS;         // [8192, 2]
    float* flatP = outP + 2 * BATCH;                 // [8192, 8192]

    __half *Ah, *Bth, *B2h, *hiddenH;
    float  *part;
    cudaGetSymbolAddress((void**)&Ah,      g_Ah);
    cudaGetSymbolAddress((void**)&Bth,     g_Bth);
    cudaGetSymbolAddress((void**)&B2h,     g_B2h);
    cudaGetSymbolAddress((void**)&hiddenH, g_hidden_h);
    cudaGetSymbolAddress((void**)&part,    g_part);

    const int gemmSmem = NSTAGE * STG_BYTES + 16;    // 61456
    cudaFuncSetAttribute(gemm_f16, cudaFuncAttributeMaxDynamicSharedMemorySize, gemmSmem);

    const int mT = (NT + 127) / 128;                 // 28

    // ===== ATT branch =====
    {
        size_t n4 = (size_t)M_PAD * (KP_ATT / 4);
        pack_A_h<<<(unsigned)((n4 + 255) / 256), 256>>>(r_att, p_att, N_RNA, SZ_R, KP_ATT, Ah);
        convertB<<<dim3(H_ATT / 32, KP_ATT / 32), dim3(32, 8)>>>(W_att1, Bth, SZ_R, KP_ATT, H_ATT);
        gemm_f16<<<dim3(H_ATT / 128, mT, 1), 256, gemmSmem>>>(
            Ah, KP_ATT, NT, Bth, KP_ATT, H_ATT, KP_ATT, b_att1, hiddenH, nullptr, 0);
        convertB<<<dim3(256 / 32, H_ATT / 32), dim3(32, 8)>>>(W_att2, B2h, H_ATT, H_ATT, 256);
        gemm_f16<<<dim3(2, mT, SPLITS2), 256, gemmSmem>>>(
            hiddenH, H_ATT, NT, B2h, H_ATT, 256, H_ATT / SPLITS2, nullptr, nullptr, part, 1);
        gemm2_reduce<<<(NT * 256 + 255) / 256, 256>>>(part, b_att2, e, NT, 0);
    }
    // ===== FUN branch =====
    {
        size_t n4 = (size_t)M_PAD * (KP_FUN / 4);
        pack_A_h<<<(unsigned)((n4 + 255) / 256), 256>>>(r_fun, p_fun, N_RNA, FUN_IN, KP_FUN, Ah);
        convertB<<<dim3(H_FUN / 32, KP_FUN / 32), dim3(32, 8)>>>(W_fun1, Bth, FUN_IN, KP_FUN, H_FUN);
        gemm_f16<<<dim3(H_FUN / 128, mT, 1), 256, gemmSmem>>>(
            Ah, KP_FUN, NT, Bth, KP_FUN, H_FUN, KP_FUN, b_fun1, hiddenH, nullptr, 0);
        convertB<<<dim3(256 / 32, H_FUN / 32), dim3(32, 8)>>>(W_fun2, B2h, H_FUN, H_FUN, 256);
        gemm_f16<<<dim3(2, mT, SPLITS2), 256, gemmSmem>>>(
            hiddenH, H_FUN, NT, B2h, H_FUN, 256, H_FUN / SPLITS2, nullptr, nullptr, part, 1);
        gemm2_reduce<<<(NT * 256 + 255) / 256, 256>>>(part, b_fun2, e, NT, 256);
    }

    // fused conv stack — unchanged (69280 B smem, 3 CTAs/SM)
    const int convSmem = 17320 * 4;
    cudaFuncSetAttribute(conv_fused, cudaFuncAttributeMaxDynamicSharedMemorySize, convSmem);
    conv_fused<<<BATCH, 256, convSmem>>>(e, idx, conv1_w, conv1_b, conv2_w, conv2_b,
                                         W_out, b_out, outP, flatP);
}